// round 4
// baseline (speedup 1.0000x reference)
#include <cuda_runtime.h>
#include <math.h>

#define BNUM 16
#define LNUM 20
#define CNUM 256
#define DT   768

typedef unsigned long long ull;

// ---------------- scratch ----------------
__device__ float g_K[BNUM*LNUM*CNUM];
__device__ float g_V[BNUM*LNUM*CNUM];
__device__ float g_M[BNUM*LNUM*CNUM];
__device__ float g_G[BNUM*LNUM*LNUM];
__device__ float g_scale[BNUM*CNUM];
__device__ float g_beta[BNUM*CNUM];
__device__ float g_vec2[BNUM*2];
__device__ int   g_maxbuf[64];
__device__ __align__(16) float g_gate_raw[348160];
__device__ __align__(16) float g_gi[348160];

// ---------------- constants for phaseA2 ----------------
__constant__ int   c_HW[4]      = {16384, 4096, 1024, 256};
__constant__ int   c_W[4]       = {128, 64, 32, 16};
__constant__ int   c_lw[4]      = {7, 6, 5, 4};
__constant__ int   c_pixBase[4] = {0, 262144, 327680, 344064};
__constant__ int   c_gateOut[4] = {89128960, 89391104, 89456640, 89473024};
__constant__ float c_step[4]    = {2.f/127.f, 2.f/63.f, 2.f/31.f, 2.f/15.f};

// ---------------- packed f32x2 helpers ----------------
__device__ __forceinline__ ull pk2(float lo, float hi) {
    ull r;
    asm("mov.b64 %0,{%1,%2};" : "=l"(r) : "f"(lo), "f"(hi));
    return r;
}
__device__ __forceinline__ void fma2(ull& d, ull a, ull b) {
    asm("fma.rn.f32x2 %0,%1,%2,%0;" : "+l"(d) : "l"(a), "l"(b));
}
__device__ __forceinline__ float2 unpk2(ull v) {
    float2 f;
    asm("mov.b64 {%0,%1},%2;" : "=f"(f.x), "=f"(f.y) : "l"(v));
    return f;
}

// ================= prep: blocks 0..79 = KV tiles (4 rows); 80..95 = mod MLPs =================
#define KV_ROWS 4
__global__ __launch_bounds__(256) void prep_kernel(
    const float* __restrict__ wt, const float* __restrict__ Wk, const float* __restrict__ Wv,
    const float* __restrict__ sent,
    const float* __restrict__ gw1, const float* __restrict__ gb1,
    const float* __restrict__ gw2, const float* __restrict__ gb2,
    const float* __restrict__ bw1, const float* __restrict__ bb1,
    const float* __restrict__ bw2, const float* __restrict__ bb2,
    const float* __restrict__ dw1, const float* __restrict__ db1,
    const float* __restrict__ dw2, const float* __restrict__ db2)
{
    __shared__ __align__(16) float swt[KV_ROWS*DT];
    __shared__ __align__(16) float ss[DT];
    __shared__ float sh[CNUM];
    int t = threadIdx.x;
    int bid = blockIdx.x;

    if (bid < 80) {
        if (bid == 0 && t < 64) g_maxbuf[t] = 0;
        int r0 = bid * KV_ROWS;
        for (int i = t; i < KV_ROWS*DT; i += 256) swt[i] = wt[(size_t)r0*DT + i];
        __syncthreads();
        float aK[KV_ROWS], aV[KV_ROWS];
#pragma unroll
        for (int r = 0; r < KV_ROWS; ++r) { aK[r] = 0.f; aV[r] = 0.f; }
        int c = t;
        for (int d = 0; d < DT; d += 4) {
            float k0 = Wk[(d+0)*CNUM + c], k1 = Wk[(d+1)*CNUM + c];
            float k2 = Wk[(d+2)*CNUM + c], k3 = Wk[(d+3)*CNUM + c];
            float v0 = Wv[(d+0)*CNUM + c], v1 = Wv[(d+1)*CNUM + c];
            float v2 = Wv[(d+2)*CNUM + c], v3 = Wv[(d+3)*CNUM + c];
#pragma unroll
            for (int r = 0; r < KV_ROWS; ++r) {
                float4 w = *reinterpret_cast<const float4*>(&swt[r*DT + d]);
                aK[r] = fmaf(w.x, k0, aK[r]); aK[r] = fmaf(w.y, k1, aK[r]);
                aK[r] = fmaf(w.z, k2, aK[r]); aK[r] = fmaf(w.w, k3, aK[r]);
                aV[r] = fmaf(w.x, v0, aV[r]); aV[r] = fmaf(w.y, v1, aV[r]);
                aV[r] = fmaf(w.z, v2, aV[r]); aV[r] = fmaf(w.w, v3, aV[r]);
            }
        }
#pragma unroll
        for (int r = 0; r < KV_ROWS; ++r) {
            g_K[(r0 + r)*CNUM + c] = aK[r];
            g_V[(r0 + r)*CNUM + c] = aV[r];
        }
    } else {
        int b = bid - 80;
        for (int i = t; i < DT; i += 256) ss[i] = sent[b*DT + i];
        __syncthreads();
        {
            float a0=0,a1=0,a2=0,a3=0;
            for (int d = 0; d < DT; d += 4) {
                float4 s = *reinterpret_cast<const float4*>(&ss[d]);
                a0 = fmaf(s.x, gw1[(d+0)*CNUM + t], a0);
                a1 = fmaf(s.y, gw1[(d+1)*CNUM + t], a1);
                a2 = fmaf(s.z, gw1[(d+2)*CNUM + t], a2);
                a3 = fmaf(s.w, gw1[(d+3)*CNUM + t], a3);
            }
            sh[t] = fmaxf((a0+a1)+(a2+a3) + gb1[t], 0.f);
        }
        __syncthreads();
        {
            float a0=0,a1=0,a2=0,a3=0;
            for (int j = 0; j < CNUM; j += 4) {
                float4 s = *reinterpret_cast<const float4*>(&sh[j]);
                a0 = fmaf(s.x, gw2[(j+0)*CNUM + t], a0);
                a1 = fmaf(s.y, gw2[(j+1)*CNUM + t], a1);
                a2 = fmaf(s.z, gw2[(j+2)*CNUM + t], a2);
                a3 = fmaf(s.w, gw2[(j+3)*CNUM + t], a3);
            }
            g_scale[b*CNUM + t] = 1.f + (a0+a1)+(a2+a3) + gb2[t];
        }
        __syncthreads();
        {
            float a0=0,a1=0,a2=0,a3=0;
            for (int d = 0; d < DT; d += 4) {
                float4 s = *reinterpret_cast<const float4*>(&ss[d]);
                a0 = fmaf(s.x, bw1[(d+0)*CNUM + t], a0);
                a1 = fmaf(s.y, bw1[(d+1)*CNUM + t], a1);
                a2 = fmaf(s.z, bw1[(d+2)*CNUM + t], a2);
                a3 = fmaf(s.w, bw1[(d+3)*CNUM + t], a3);
            }
            sh[t] = fmaxf((a0+a1)+(a2+a3) + bb1[t], 0.f);
        }
        __syncthreads();
        {
            float a0=0,a1=0,a2=0,a3=0;
            for (int j = 0; j < CNUM; j += 4) {
                float4 s = *reinterpret_cast<const float4*>(&sh[j]);
                a0 = fmaf(s.x, bw2[(j+0)*CNUM + t], a0);
                a1 = fmaf(s.y, bw2[(j+1)*CNUM + t], a1);
                a2 = fmaf(s.z, bw2[(j+2)*CNUM + t], a2);
                a3 = fmaf(s.w, bw2[(j+3)*CNUM + t], a3);
            }
            g_beta[b*CNUM + t] = (a0+a1)+(a2+a3) + bb2[t];
        }
        __syncthreads();
        if (t < 64) {
            float a0=0,a1=0,a2=0,a3=0;
            for (int d = 0; d < DT; d += 4) {
                float4 s = *reinterpret_cast<const float4*>(&ss[d]);
                a0 = fmaf(s.x, dw1[(d+0)*64 + t], a0);
                a1 = fmaf(s.y, dw1[(d+1)*64 + t], a1);
                a2 = fmaf(s.z, dw1[(d+2)*64 + t], a2);
                a3 = fmaf(s.w, dw1[(d+3)*64 + t], a3);
            }
            sh[t] = fmaxf((a0+a1)+(a2+a3) + db1[t], 0.f);
        }
        __syncthreads();
        if (t == 0) {
            float v0 = db2[0], v1 = db2[1];
            for (int j = 0; j < 64; ++j) {
                v0 = fmaf(sh[j], dw2[j*2 + 0], v0);
                v1 = fmaf(sh[j], dw2[j*2 + 1], v1);
            }
            float nrm = fmaxf(sqrtf(v0*v0 + v1*v1), 1e-12f);
            g_vec2[b*2 + 0] = v0 / nrm;
            g_vec2[b*2 + 1] = v1 / nrm;
        }
    }
}

// ================= blocks 0..79: M = (K@Wq)/16 (4 rows); 80..95: G = V@V^T =================
__global__ __launch_bounds__(256) void mv_kernel(const float* __restrict__ Wq) {
    __shared__ __align__(16) float sK[KV_ROWS*CNUM];
    __shared__ __align__(16) float sV[LNUM*CNUM];
    int t = threadIdx.x;
    int bid = blockIdx.x;
    if (bid < 80) {
        int r0 = bid * KV_ROWS;
        for (int i = t; i < KV_ROWS*CNUM; i += 256) sK[i] = g_K[r0*CNUM + i];
        __syncthreads();
        float acc[KV_ROWS];
#pragma unroll
        for (int r = 0; r < KV_ROWS; ++r) acc[r] = 0.f;
        int c = t;
        for (int o = 0; o < CNUM; o += 4) {
            float q0 = Wq[(o+0)*CNUM + c], q1 = Wq[(o+1)*CNUM + c];
            float q2 = Wq[(o+2)*CNUM + c], q3 = Wq[(o+3)*CNUM + c];
#pragma unroll
            for (int r = 0; r < KV_ROWS; ++r) {
                float4 k = *reinterpret_cast<const float4*>(&sK[r*CNUM + o]);
                acc[r] = fmaf(k.x, q0, acc[r]); acc[r] = fmaf(k.y, q1, acc[r]);
                acc[r] = fmaf(k.z, q2, acc[r]); acc[r] = fmaf(k.w, q3, acc[r]);
            }
        }
#pragma unroll
        for (int r = 0; r < KV_ROWS; ++r)
            g_M[(r0 + r)*CNUM + c] = acc[r] * 0.0625f;
    } else {
        int b = bid - 80;
        for (int i = t; i < LNUM*CNUM; i += 256) sV[i] = g_V[b*LNUM*CNUM + i];
        __syncthreads();
        for (int e = t; e < LNUM*LNUM; e += 256) {
            int l  = e / LNUM;
            int l2 = e % LNUM;
            float a0=0,a1=0,a2=0,a3=0;
            for (int c = 0; c < CNUM; c += 4) {
                float4 x = *reinterpret_cast<const float4*>(&sV[l*CNUM + c]);
                float4 y = *reinterpret_cast<const float4*>(&sV[l2*CNUM + c]);
                a0 = fmaf(x.x, y.x, a0); a1 = fmaf(x.y, y.y, a1);
                a2 = fmaf(x.z, y.z, a2); a3 = fmaf(x.w, y.w, a3);
            }
            g_G[b*LNUM*LNUM + e] = (a0+a1)+(a2+a3);
        }
    }
}

// ================= Phase A: templated per level, pixel-packed accumulators =================
template<int HW, int PPT, int NT>
__global__ __launch_bounds__(NT) void phaseA_t(const float* __restrict__ F,
                                               const int* __restrict__ mask,
                                               int pixBase, int maxIdx) {
    constexpr int TILE = NT * PPT;
    constexpr int TPB  = HW / TILE;      // tiles per batch
    constexpr int NP   = PPT / 2;        // packed pixel pairs per thread
    __shared__ __align__(16) ull sM2[LNUM*CNUM];      // (m,m) pairs, 40KB
    __shared__ __align__(16) ull sG2[LNUM*LNUM];      // (g,g) pairs
    __shared__ int smask[LNUM];

    int b    = blockIdx.x / TPB;
    int tile = blockIdx.x - b * TPB;
    int t    = threadIdx.x;
    int bbase = b * LNUM * CNUM;
    for (int i = t; i < LNUM*CNUM; i += NT) { float m = g_M[bbase + i]; sM2[i] = pk2(m, m); }
    for (int i = t; i < LNUM*LNUM; i += NT) { float g = g_G[b*LNUM*LNUM + i]; sG2[i] = pk2(g, g); }
    if (t < LNUM) smask[t] = mask[b*LNUM + t];
    __syncthreads();

    int n0 = tile * TILE + t * PPT;
    const float* p = F + (size_t)b * CNUM * HW + n0;

    ull acc[LNUM][NP];
#pragma unroll
    for (int l = 0; l < LNUM; ++l)
#pragma unroll
        for (int j = 0; j < NP; ++j) acc[l][j] = 0ull;

    // logits: acc[l] packed over pixels; F loads feed FFMA2 directly (no repacking)
#pragma unroll 2
    for (int c = 0; c < CNUM; c += 2) {
        ull fa[NP], fb[NP];
        if (PPT == 4) {
            ulonglong2 A  = *reinterpret_cast<const ulonglong2*>(p);
            ulonglong2 Bv = *reinterpret_cast<const ulonglong2*>(p + HW);
            fa[0] = A.x;  fa[NP-1] = A.y;
            fb[0] = Bv.x; fb[NP-1] = Bv.y;
        } else {
            fa[0] = *reinterpret_cast<const ull*>(p);
            fb[0] = *reinterpret_cast<const ull*>(p + HW);
        }
        p += 2 * HW;
#pragma unroll
        for (int l = 0; l < LNUM; ++l) {
            ulonglong2 m = *reinterpret_cast<const ulonglong2*>(&sM2[l*CNUM + c]);
#pragma unroll
            for (int j = 0; j < NP; ++j) {
                fma2(acc[l][j], fa[j], m.x);
                fma2(acc[l][j], fb[j], m.y);
            }
        }
    }

    // lane-wise masked softmax (in place; normalization folded into gate)
    float2 mx[NP], sm[NP];
#pragma unroll
    for (int j = 0; j < NP; ++j) { mx[j] = make_float2(-1e30f, -1e30f); sm[j] = make_float2(0.f, 0.f); }
#pragma unroll
    for (int l = 0; l < LNUM; ++l) {
        if (smask[l]) {
#pragma unroll
            for (int j = 0; j < NP; ++j) {
                float2 u = unpk2(acc[l][j]);
                mx[j].x = fmaxf(mx[j].x, u.x);
                mx[j].y = fmaxf(mx[j].y, u.y);
            }
        }
    }
#pragma unroll
    for (int l = 0; l < LNUM; ++l) {
        int mk = smask[l];
#pragma unroll
        for (int j = 0; j < NP; ++j) {
            float2 u = unpk2(acc[l][j]);
            float e0 = mk ? __expf(u.x - mx[j].x) : 0.f;
            float e1 = mk ? __expf(u.y - mx[j].y) : 0.f;
            sm[j].x += e0; sm[j].y += e1;
            acc[l][j] = pk2(e0, e1);
        }
    }

    // gate = sqrt(e^T G e) / sum(e)
    ull gs[NP];
#pragma unroll
    for (int j = 0; j < NP; ++j) gs[j] = 0ull;
#pragma unroll
    for (int l = 0; l < LNUM; ++l) {
        ull tt[NP];
#pragma unroll
        for (int j = 0; j < NP; ++j) tt[j] = 0ull;
#pragma unroll
        for (int l2 = 0; l2 < LNUM; l2 += 2) {
            ulonglong2 gg = *reinterpret_cast<const ulonglong2*>(&sG2[l*LNUM + l2]);
#pragma unroll
            for (int j = 0; j < NP; ++j) {
                fma2(tt[j], acc[l2][j],   gg.x);
                fma2(tt[j], acc[l2+1][j], gg.y);
            }
        }
#pragma unroll
        for (int j = 0; j < NP; ++j) fma2(gs[j], acc[l][j], tt[j]);
    }

    int pbase = pixBase + b * HW;
    if (PPT == 4) {
        float2 g0 = unpk2(gs[0]), g1 = unpk2(gs[NP-1]);
        float4 gt;
        gt.x = sqrtf(fmaxf(g0.x, 0.f)) * __fdividef(1.f, sm[0].x);
        gt.y = sqrtf(fmaxf(g0.y, 0.f)) * __fdividef(1.f, sm[0].y);
        gt.z = sqrtf(fmaxf(g1.x, 0.f)) * __fdividef(1.f, sm[NP-1].x);
        gt.w = sqrtf(fmaxf(g1.y, 0.f)) * __fdividef(1.f, sm[NP-1].y);
        *reinterpret_cast<float4*>(&g_gate_raw[pbase + n0]) = gt;
        float m01 = fmaxf(gt.x, gt.y), m23 = fmaxf(gt.z, gt.w);
        atomicMax(&g_maxbuf[maxIdx + b], __float_as_int(fmaxf(m01, m23)));
    } else {
        float2 g0 = unpk2(gs[0]);
        float2 gt;
        gt.x = sqrtf(fmaxf(g0.x, 0.f)) * __fdividef(1.f, sm[0].x);
        gt.y = sqrtf(fmaxf(g0.y, 0.f)) * __fdividef(1.f, sm[0].y);
        *reinterpret_cast<float2*>(&g_gate_raw[pbase + n0]) = gt;
        atomicMax(&g_maxbuf[maxIdx + b], __float_as_int(fmaxf(gt.x, gt.y)));
    }
}

// ---------------- decode for phaseA2 (688 blocks, 512 px each) ----------------
__device__ __forceinline__ void decode_block(int bid, int& level, int& b, int& tile) {
    if (bid < 512)      { level = 0; b = bid >> 5; tile = bid & 31; }
    else if (bid < 640) { int r = bid - 512; level = 1; b = r >> 3; tile = r & 7; }
    else if (bid < 672) { int r = bid - 640; level = 2; b = r >> 1; tile = r & 1; }
    else                { level = 3; b = bid - 672; tile = 0; }
}

// ================= Phase A2 =================
__global__ __launch_bounds__(256) void phaseA2(float* __restrict__ out) {
    int level, b, tile;
    decode_block(blockIdx.x, level, b, tile);
    int t = threadIdx.x;
    const int HW = c_HW[level];
    const int W  = c_W[level];
    const int lw = c_lw[level];
    float step = c_step[level];
    float v0 = g_vec2[2*b], v1 = g_vec2[2*b + 1];
    float mxv = __int_as_float(g_maxbuf[level*16 + b]) + 1e-6f;
    int pbase = c_pixBase[level] + b*HW;
    int obase = c_gateOut[level] + b*HW;
#pragma unroll
    for (int p = 0; p < 2; ++p) {
        int n = tile * 512 + t + p * 256;
        if (n >= HW) break;
        int w = n & (W - 1);
        int h = n >> lw;
        float x = fmaf((float)w, step, -1.f);
        float y = fmaf((float)h, step, -1.f);
        float pr = v0 * x + v1 * y;
        float di = __fdividef(1.f, 1.f + __expf(-pr));
        float gi = __fdividef(g_gate_raw[pbase + n], mxv) * di;
        g_gi[pbase + n] = gi;
        out[obase + n] = gi;
    }
}

// ================= Phase B: templated per level, linear addressing =================
template<int HW, int LG>
__global__ __launch_bounds__(256) void phaseB_t(const float* __restrict__ F,
                                                float* __restrict__ out,
                                                int pixBase) {
    int g = blockIdx.x * 512 + threadIdx.x * 2;     // float4 index within level (2 consecutive)
    int n4   = g & (HW/4 - 1);
    int rest = g >> LG;
    int c = rest & 255;
    int b = rest >> 8;
    float sc = g_scale[b*CNUM + c];
    float be = g_beta[b*CNUM + c];
    const float4* fp = reinterpret_cast<const float4*>(F) + g;
    const float4* gp = reinterpret_cast<const float4*>(&g_gi[pixBase + b*HW]) + n4;
    float4*       op = reinterpret_cast<float4*>(out) + g;
#pragma unroll
    for (int j = 0; j < 2; ++j) {
        float4 f  = fp[j];
        float4 gi = gp[j];
        float4 o;
        o.x = fmaf(gi.x * f.x, sc, be);
        o.y = fmaf(gi.y * f.y, sc, be);
        o.z = fmaf(gi.z * f.z, sc, be);
        o.w = fmaf(gi.w * f.w, sc, be);
        op[j] = o;
    }
}

// ================= launch =================
extern "C" void kernel_launch(void* const* d_in, const int* in_sizes, int n_in,
                              void* d_out, int out_size) {
    const float* f0   = (const float*)d_in[0];
    const float* f1   = (const float*)d_in[1];
    const float* f2   = (const float*)d_in[2];
    const float* f3   = (const float*)d_in[3];
    const float* wt   = (const float*)d_in[4];
    const float* sent = (const float*)d_in[5];
    const int*   mask = (const int*)  d_in[6];
    const float* Wq   = (const float*)d_in[7];
    const float* Wk   = (const float*)d_in[8];
    const float* Wv   = (const float*)d_in[9];
    const float* gw1  = (const float*)d_in[10];
    const float* gb1  = (const float*)d_in[11];
    const float* gw2  = (const float*)d_in[12];
    const float* gb2  = (const float*)d_in[13];
    const float* bw1  = (const float*)d_in[14];
    const float* bb1  = (const float*)d_in[15];
    const float* bw2  = (const float*)d_in[16];
    const float* bb2  = (const float*)d_in[17];
    const float* dw1  = (const float*)d_in[18];
    const float* db1  = (const float*)d_in[19];
    const float* dw2  = (const float*)d_in[20];
    const float* db2  = (const float*)d_in[21];
    float* out = (float*)d_out;

    prep_kernel<<<96, 256>>>(wt, Wk, Wv, sent, gw1, gb1, gw2, gb2,
                             bw1, bb1, bw2, bb2, dw1, db1, dw2, db2);
    mv_kernel<<<96, 256>>>(Wq);

    phaseA_t<16384, 4, 256><<<256, 256>>>(f0, mask, 0,       0);
    phaseA_t< 4096, 4, 256><<< 64, 256>>>(f1, mask, 262144, 16);
    phaseA_t< 1024, 4, 256><<< 16, 256>>>(f2, mask, 327680, 32);
    phaseA_t<  256, 2, 128><<< 16, 128>>>(f3, mask, 344064, 48);

    phaseA2<<<688, 256>>>(out);

    phaseB_t<16384, 12><<<32768, 256>>>(f0, out,            0);
    phaseB_t< 4096, 10><<< 8192, 256>>>(f1, out + 67108864, 262144);
    phaseB_t< 1024,  8><<< 2048, 256>>>(f2, out + 83886080, 327680);
    phaseB_t<  256,  6><<<  512, 256>>>(f3, out + 88080384, 344064);
}

// round 5
// speedup vs baseline: 1.2788x; 1.2788x over previous
#include <cuda_runtime.h>
#include <math.h>

#define BNUM 16
#define LNUM 20
#define CNUM 256
#define DT   768

typedef unsigned long long ull;

// ---------------- scratch ----------------
__device__ float g_K[BNUM*LNUM*CNUM];
__device__ float g_V[BNUM*LNUM*CNUM];
__device__ float g_M[BNUM*LNUM*CNUM];
__device__ float g_G[BNUM*LNUM*LNUM];
__device__ float g_scale[BNUM*CNUM];
__device__ float g_beta[BNUM*CNUM];
__device__ float g_vec2[BNUM*2];
__device__ int   g_maxbuf[64];
__device__ __align__(16) float g_gate_raw[348160];
__device__ __align__(16) float g_gi[348160];

// ---------------- constants ----------------
__constant__ int   c_HW[4]      = {16384, 4096, 1024, 256};
__constant__ int   c_W[4]       = {128, 64, 32, 16};
__constant__ int   c_lw[4]      = {7, 6, 5, 4};
__constant__ int   c_pixBase[4] = {0, 262144, 327680, 344064};
__constant__ int   c_gateOut[4] = {89128960, 89391104, 89456640, 89473024};
__constant__ float c_step[4]    = {2.f/127.f, 2.f/63.f, 2.f/31.f, 2.f/15.f};

// ---------------- packed f32x2 helpers ----------------
__device__ __forceinline__ ull pk2(float lo, float hi) {
    ull r;
    asm("mov.b64 %0,{%1,%2};" : "=l"(r) : "f"(lo), "f"(hi));
    return r;
}
__device__ __forceinline__ void fma2(ull& d, ull a, ull b) {
    asm("fma.rn.f32x2 %0,%1,%2,%0;" : "+l"(d) : "l"(a), "l"(b));
}
__device__ __forceinline__ float2 unpk2(ull v) {
    float2 f;
    asm("mov.b64 {%0,%1},%2;" : "=f"(f.x), "=f"(f.y) : "l"(v));
    return f;
}

// ================= prep: blocks 0..79 = KV tiles (4 rows); 80..95 = mod MLPs =================
#define KV_ROWS 4
__global__ __launch_bounds__(256) void prep_kernel(
    const float* __restrict__ wt, const float* __restrict__ Wk, const float* __restrict__ Wv,
    const float* __restrict__ sent,
    const float* __restrict__ gw1, const float* __restrict__ gb1,
    const float* __restrict__ gw2, const float* __restrict__ gb2,
    const float* __restrict__ bw1, const float* __restrict__ bb1,
    const float* __restrict__ bw2, const float* __restrict__ bb2,
    const float* __restrict__ dw1, const float* __restrict__ db1,
    const float* __restrict__ dw2, const float* __restrict__ db2)
{
    __shared__ __align__(16) float swt[KV_ROWS*DT];
    __shared__ __align__(16) float ss[DT];
    __shared__ float sh[CNUM];
    int t = threadIdx.x;
    int bid = blockIdx.x;

    if (bid < 80) {
        if (bid == 0 && t < 64) g_maxbuf[t] = 0;
        int r0 = bid * KV_ROWS;
        for (int i = t; i < KV_ROWS*DT; i += 256) swt[i] = wt[(size_t)r0*DT + i];
        __syncthreads();
        float aK[KV_ROWS], aV[KV_ROWS];
#pragma unroll
        for (int r = 0; r < KV_ROWS; ++r) { aK[r] = 0.f; aV[r] = 0.f; }
        int c = t;
        for (int d = 0; d < DT; d += 4) {
            float k0 = Wk[(d+0)*CNUM + c], k1 = Wk[(d+1)*CNUM + c];
            float k2 = Wk[(d+2)*CNUM + c], k3 = Wk[(d+3)*CNUM + c];
            float v0 = Wv[(d+0)*CNUM + c], v1 = Wv[(d+1)*CNUM + c];
            float v2 = Wv[(d+2)*CNUM + c], v3 = Wv[(d+3)*CNUM + c];
#pragma unroll
            for (int r = 0; r < KV_ROWS; ++r) {
                float4 w = *reinterpret_cast<const float4*>(&swt[r*DT + d]);
                aK[r] = fmaf(w.x, k0, aK[r]); aK[r] = fmaf(w.y, k1, aK[r]);
                aK[r] = fmaf(w.z, k2, aK[r]); aK[r] = fmaf(w.w, k3, aK[r]);
                aV[r] = fmaf(w.x, v0, aV[r]); aV[r] = fmaf(w.y, v1, aV[r]);
                aV[r] = fmaf(w.z, v2, aV[r]); aV[r] = fmaf(w.w, v3, aV[r]);
            }
        }
#pragma unroll
        for (int r = 0; r < KV_ROWS; ++r) {
            g_K[(r0 + r)*CNUM + c] = aK[r];
            g_V[(r0 + r)*CNUM + c] = aV[r];
        }
    } else {
        int b = bid - 80;
        for (int i = t; i < DT; i += 256) ss[i] = sent[b*DT + i];
        __syncthreads();
        {
            float a0=0,a1=0,a2=0,a3=0;
            for (int d = 0; d < DT; d += 4) {
                float4 s = *reinterpret_cast<const float4*>(&ss[d]);
                a0 = fmaf(s.x, gw1[(d+0)*CNUM + t], a0);
                a1 = fmaf(s.y, gw1[(d+1)*CNUM + t], a1);
                a2 = fmaf(s.z, gw1[(d+2)*CNUM + t], a2);
                a3 = fmaf(s.w, gw1[(d+3)*CNUM + t], a3);
            }
            sh[t] = fmaxf((a0+a1)+(a2+a3) + gb1[t], 0.f);
        }
        __syncthreads();
        {
            float a0=0,a1=0,a2=0,a3=0;
            for (int j = 0; j < CNUM; j += 4) {
                float4 s = *reinterpret_cast<const float4*>(&sh[j]);
                a0 = fmaf(s.x, gw2[(j+0)*CNUM + t], a0);
                a1 = fmaf(s.y, gw2[(j+1)*CNUM + t], a1);
                a2 = fmaf(s.z, gw2[(j+2)*CNUM + t], a2);
                a3 = fmaf(s.w, gw2[(j+3)*CNUM + t], a3);
            }
            g_scale[b*CNUM + t] = 1.f + (a0+a1)+(a2+a3) + gb2[t];
        }
        __syncthreads();
        {
            float a0=0,a1=0,a2=0,a3=0;
            for (int d = 0; d < DT; d += 4) {
                float4 s = *reinterpret_cast<const float4*>(&ss[d]);
                a0 = fmaf(s.x, bw1[(d+0)*CNUM + t], a0);
                a1 = fmaf(s.y, bw1[(d+1)*CNUM + t], a1);
                a2 = fmaf(s.z, bw1[(d+2)*CNUM + t], a2);
                a3 = fmaf(s.w, bw1[(d+3)*CNUM + t], a3);
            }
            sh[t] = fmaxf((a0+a1)+(a2+a3) + bb1[t], 0.f);
        }
        __syncthreads();
        {
            float a0=0,a1=0,a2=0,a3=0;
            for (int j = 0; j < CNUM; j += 4) {
                float4 s = *reinterpret_cast<const float4*>(&sh[j]);
                a0 = fmaf(s.x, bw2[(j+0)*CNUM + t], a0);
                a1 = fmaf(s.y, bw2[(j+1)*CNUM + t], a1);
                a2 = fmaf(s.z, bw2[(j+2)*CNUM + t], a2);
                a3 = fmaf(s.w, bw2[(j+3)*CNUM + t], a3);
            }
            g_beta[b*CNUM + t] = (a0+a1)+(a2+a3) + bb2[t];
        }
        __syncthreads();
        if (t < 64) {
            float a0=0,a1=0,a2=0,a3=0;
            for (int d = 0; d < DT; d += 4) {
                float4 s = *reinterpret_cast<const float4*>(&ss[d]);
                a0 = fmaf(s.x, dw1[(d+0)*64 + t], a0);
                a1 = fmaf(s.y, dw1[(d+1)*64 + t], a1);
                a2 = fmaf(s.z, dw1[(d+2)*64 + t], a2);
                a3 = fmaf(s.w, dw1[(d+3)*64 + t], a3);
            }
            sh[t] = fmaxf((a0+a1)+(a2+a3) + db1[t], 0.f);
        }
        __syncthreads();
        if (t == 0) {
            float v0 = db2[0], v1 = db2[1];
            for (int j = 0; j < 64; ++j) {
                v0 = fmaf(sh[j], dw2[j*2 + 0], v0);
                v1 = fmaf(sh[j], dw2[j*2 + 1], v1);
            }
            float nrm = fmaxf(sqrtf(v0*v0 + v1*v1), 1e-12f);
            g_vec2[b*2 + 0] = v0 / nrm;
            g_vec2[b*2 + 1] = v1 / nrm;
        }
    }
}

// ================= blocks 0..79: M = (K@Wq)/16; 80..95: G = V@V^T =================
__global__ __launch_bounds__(256) void mv_kernel(const float* __restrict__ Wq) {
    __shared__ __align__(16) float sK[KV_ROWS*CNUM];
    __shared__ __align__(16) float sV[LNUM*CNUM];
    int t = threadIdx.x;
    int bid = blockIdx.x;
    if (bid < 80) {
        int r0 = bid * KV_ROWS;
        for (int i = t; i < KV_ROWS*CNUM; i += 256) sK[i] = g_K[r0*CNUM + i];
        __syncthreads();
        float acc[KV_ROWS];
#pragma unroll
        for (int r = 0; r < KV_ROWS; ++r) acc[r] = 0.f;
        int c = t;
        for (int o = 0; o < CNUM; o += 4) {
            float q0 = Wq[(o+0)*CNUM + c], q1 = Wq[(o+1)*CNUM + c];
            float q2 = Wq[(o+2)*CNUM + c], q3 = Wq[(o+3)*CNUM + c];
#pragma unroll
            for (int r = 0; r < KV_ROWS; ++r) {
                float4 k = *reinterpret_cast<const float4*>(&sK[r*CNUM + o]);
                acc[r] = fmaf(k.x, q0, acc[r]); acc[r] = fmaf(k.y, q1, acc[r]);
                acc[r] = fmaf(k.z, q2, acc[r]); acc[r] = fmaf(k.w, q3, acc[r]);
            }
        }
#pragma unroll
        for (int r = 0; r < KV_ROWS; ++r)
            g_M[(r0 + r)*CNUM + c] = acc[r] * 0.0625f;
    } else {
        int b = bid - 80;
        for (int i = t; i < LNUM*CNUM; i += 256) sV[i] = g_V[b*LNUM*CNUM + i];
        __syncthreads();
        for (int e = t; e < LNUM*LNUM; e += 256) {
            int l  = e / LNUM;
            int l2 = e % LNUM;
            float a0=0,a1=0,a2=0,a3=0;
            for (int c = 0; c < CNUM; c += 4) {
                float4 x = *reinterpret_cast<const float4*>(&sV[l*CNUM + c]);
                float4 y = *reinterpret_cast<const float4*>(&sV[l2*CNUM + c]);
                a0 = fmaf(x.x, y.x, a0); a1 = fmaf(x.y, y.y, a1);
                a2 = fmaf(x.z, y.z, a2); a3 = fmaf(x.w, y.w, a3);
            }
            g_G[b*LNUM*LNUM + e] = (a0+a1)+(a2+a3);
        }
    }
}

// ---------------- block decode: 688 blocks ----------------
__device__ __forceinline__ void decode_block(int bid, int& level, int& b, int& tile) {
    if (bid < 512)      { level = 0; b = bid >> 5; tile = bid & 31; }
    else if (bid < 640) { int r = bid - 512; level = 1; b = r >> 3; tile = r & 7; }
    else if (bid < 672) { int r = bid - 640; level = 2; b = r >> 1; tile = r & 1; }
    else                { level = 3; b = bid - 672; tile = 0; }
}

// ---------------- phaseA core: compile-time HW, 2 adjacent pixels/thread ----------------
template<int HW>
__device__ __forceinline__ void phaseA_core(const float* __restrict__ F, int b, int n0,
                                            const ull* __restrict__ sM2,
                                            const ull* __restrict__ sG2,
                                            const int* __restrict__ smask,
                                            int pbase, int maxSlot) {
    const float* p = F + (size_t)b * CNUM * HW + n0;

    ull acc[LNUM];
#pragma unroll
    for (int l = 0; l < LNUM; ++l) acc[l] = 0ull;

    // logits: pixel-packed — LDG.64 of the pixel pair IS the FFMA2 operand
#pragma unroll 4
    for (int c = 0; c < CNUM; c += 2) {
        ull fa = *reinterpret_cast<const ull*>(p);
        ull fb = *reinterpret_cast<const ull*>(p + HW);
        p += 2 * HW;
#pragma unroll
        for (int l = 0; l < LNUM; ++l) {
            ulonglong2 m = *reinterpret_cast<const ulonglong2*>(&sM2[l*CNUM + c]);
            fma2(acc[l], fa, m.x);
            fma2(acc[l], fb, m.y);
        }
    }

    // lane-wise masked softmax (normalization folded into gate)
    float2 mx = make_float2(-1e30f, -1e30f);
#pragma unroll
    for (int l = 0; l < LNUM; ++l) {
        if (smask[l]) {
            float2 u = unpk2(acc[l]);
            mx.x = fmaxf(mx.x, u.x);
            mx.y = fmaxf(mx.y, u.y);
        }
    }
    float2 sm = make_float2(0.f, 0.f);
#pragma unroll
    for (int l = 0; l < LNUM; ++l) {
        int mk = smask[l];
        float2 u = unpk2(acc[l]);
        float e0 = mk ? __expf(u.x - mx.x) : 0.f;
        float e1 = mk ? __expf(u.y - mx.y) : 0.f;
        sm.x += e0; sm.y += e1;
        acc[l] = pk2(e0, e1);
    }

    // gate = sqrt(e^T G e) / sum(e)
    ull gs = 0ull;
#pragma unroll
    for (int l = 0; l < LNUM; ++l) {
        ull tt = 0ull;
#pragma unroll
        for (int l2 = 0; l2 < LNUM; l2 += 2) {
            ulonglong2 gg = *reinterpret_cast<const ulonglong2*>(&sG2[l*LNUM + l2]);
            fma2(tt, acc[l2],   gg.x);
            fma2(tt, acc[l2+1], gg.y);
        }
        fma2(gs, acc[l], tt);
    }
    float2 g0 = unpk2(gs);
    float2 gt;
    gt.x = sqrtf(fmaxf(g0.x, 0.f)) * __fdividef(1.f, sm.x);
    gt.y = sqrtf(fmaxf(g0.y, 0.f)) * __fdividef(1.f, sm.y);
    *reinterpret_cast<float2*>(&g_gate_raw[pbase + n0]) = gt;
    atomicMax(&g_maxbuf[maxSlot], __float_as_int(fmaxf(gt.x, gt.y)));
}

// ================= Phase A: one launch, level switch with compile-time HW =================
__global__ __launch_bounds__(256, 2) void phaseA(const float* __restrict__ f0,
                                                 const float* __restrict__ f1,
                                                 const float* __restrict__ f2,
                                                 const float* __restrict__ f3,
                                                 const int* __restrict__ mask) {
    __shared__ __align__(16) ull sM2[LNUM*CNUM];   // (m,m) pairs, 40KB
    __shared__ __align__(16) ull sG2[LNUM*LNUM];   // (g,g) pairs
    __shared__ int smask[LNUM];

    int level, b, tile;
    decode_block(blockIdx.x, level, b, tile);
    int t = threadIdx.x;
    int bbase = b * LNUM * CNUM;
    for (int i = t; i < LNUM*CNUM; i += 256) { float m = g_M[bbase + i]; sM2[i] = pk2(m, m); }
    for (int i = t; i < LNUM*LNUM; i += 256) { float g = g_G[b*LNUM*LNUM + i]; sG2[i] = pk2(g, g); }
    if (t < LNUM) smask[t] = mask[b*LNUM + t];
    __syncthreads();

    int n0 = tile * 512 + 2 * t;
    if (level == 0)
        phaseA_core<16384>(f0, b, n0, sM2, sG2, smask, b*16384,          b);
    else if (level == 1)
        phaseA_core< 4096>(f1, b, n0, sM2, sG2, smask, 262144 + b*4096, 16 + b);
    else if (level == 2)
        phaseA_core< 1024>(f2, b, n0, sM2, sG2, smask, 327680 + b*1024, 32 + b);
    else if (t < 128)
        phaseA_core<  256>(f3, b, 2*t, sM2, sG2, smask, 344064 + b*256, 48 + b);
}

// ================= Phase A2 =================
__global__ __launch_bounds__(256) void phaseA2(float* __restrict__ out) {
    int level, b, tile;
    decode_block(blockIdx.x, level, b, tile);
    int t = threadIdx.x;
    const int HW = c_HW[level];
    const int W  = c_W[level];
    const int lw = c_lw[level];
    float step = c_step[level];
    float v0 = g_vec2[2*b], v1 = g_vec2[2*b + 1];
    float mxv = __int_as_float(g_maxbuf[level*16 + b]) + 1e-6f;
    int pbase = c_pixBase[level] + b*HW;
    int obase = c_gateOut[level] + b*HW;
#pragma unroll
    for (int p = 0; p < 2; ++p) {
        int n = tile * 512 + t + p * 256;
        if (n >= HW) break;
        int w = n & (W - 1);
        int h = n >> lw;
        float x = fmaf((float)w, step, -1.f);
        float y = fmaf((float)h, step, -1.f);
        float pr = v0 * x + v1 * y;
        float di = __fdividef(1.f, 1.f + __expf(-pr));
        float gi = __fdividef(g_gate_raw[pbase + n], mxv) * di;
        g_gi[pbase + n] = gi;
        out[obase + n] = gi;
    }
}

// ================= Phase B: one launch, per-block level, 4 consecutive float4/thread =================
template<int HW, int LG>
__device__ __forceinline__ void phaseB_core(const float* __restrict__ F,
                                            float* __restrict__ out,
                                            int g, int pixBase) {
    int n4   = g & (HW/4 - 1);
    int rest = g >> LG;
    int c = rest & 255;
    int b = rest >> 8;
    float sc = g_scale[b*CNUM + c];
    float be = g_beta[b*CNUM + c];
    const float4* fp = reinterpret_cast<const float4*>(F) + g;
    const float4* gp = reinterpret_cast<const float4*>(&g_gi[pixBase + b*HW]) + n4;
    float4*       op = reinterpret_cast<float4*>(out) + g;
#pragma unroll
    for (int j = 0; j < 4; ++j) {
        float4 f  = fp[j];
        float4 gi = gp[j];
        float4 o;
        o.x = fmaf(gi.x * f.x, sc, be);
        o.y = fmaf(gi.y * f.y, sc, be);
        o.z = fmaf(gi.z * f.z, sc, be);
        o.w = fmaf(gi.w * f.w, sc, be);
        op[j] = o;
    }
}

__global__ __launch_bounds__(256) void phaseB(const float* __restrict__ f0,
                                              const float* __restrict__ f1,
                                              const float* __restrict__ f2,
                                              const float* __restrict__ f3,
                                              float* __restrict__ out) {
    // float4 totals per level: L0 16777216, L1 4194304, L2 1048576, L3 262144 (all /1024)
    int bid = blockIdx.x;
    int t = threadIdx.x;
    if (bid < 16384) {
        int g = bid * 1024 + t * 4;
        phaseB_core<16384, 12>(f0, out, g, 0);
    } else if (bid < 20480) {
        int g = (bid - 16384) * 1024 + t * 4;
        phaseB_core<4096, 10>(f1, out + 67108864, g, 262144);
    } else if (bid < 21504) {
        int g = (bid - 20480) * 1024 + t * 4;
        phaseB_core<1024, 8>(f2, out + 83886080, g, 327680);
    } else {
        int g = (bid - 21504) * 1024 + t * 4;
        phaseB_core<256, 6>(f3, out + 88080384, g, 344064);
    }
}

// ================= launch =================
extern "C" void kernel_launch(void* const* d_in, const int* in_sizes, int n_in,
                              void* d_out, int out_size) {
    const float* f0   = (const float*)d_in[0];
    const float* f1   = (const float*)d_in[1];
    const float* f2   = (const float*)d_in[2];
    const float* f3   = (const float*)d_in[3];
    const float* wt   = (const float*)d_in[4];
    const float* sent = (const float*)d_in[5];
    const int*   mask = (const int*)  d_in[6];
    const float* Wq   = (const float*)d_in[7];
    const float* Wk   = (const float*)d_in[8];
    const float* Wv   = (const float*)d_in[9];
    const float* gw1  = (const float*)d_in[10];
    const float* gb1  = (const float*)d_in[11];
    const float* gw2  = (const float*)d_in[12];
    const float* gb2  = (const float*)d_in[13];
    const float* bw1  = (const float*)d_in[14];
    const float* bb1  = (const float*)d_in[15];
    const float* bw2  = (const float*)d_in[16];
    const float* bb2  = (const float*)d_in[17];
    const float* dw1  = (const float*)d_in[18];
    const float* db1  = (const float*)d_in[19];
    const float* dw2  = (const float*)d_in[20];
    const float* db2  = (const float*)d_in[21];
    float* out = (float*)d_out;

    prep_kernel<<<96, 256>>>(wt, Wk, Wv, sent, gw1, gb1, gw2, gb2,
                             bw1, bb1, bw2, bb2, dw1, db1, dw2, db2);
    mv_kernel<<<96, 256>>>(Wq);
    phaseA<<<688, 256>>>(f0, f1, f2, f3, mask);
    phaseA2<<<688, 256>>>(out);
    phaseB<<<21760, 256>>>(f0, f1, f2, f3, out);
}

// round 6
// speedup vs baseline: 1.6680x; 1.3043x over previous
#include <cuda_runtime.h>
#include <math.h>

#define BNUM 16
#define LNUM 20
#define CNUM 256
#define DT   768

typedef unsigned long long ull;

// ---------------- scratch ----------------
__device__ float g_K[BNUM*LNUM*CNUM];
__device__ float g_V[BNUM*LNUM*CNUM];
__device__ float g_M[BNUM*LNUM*CNUM];
__device__ float g_G[BNUM*LNUM*LNUM];
__device__ float g_scale[BNUM*CNUM];
__device__ float g_beta[BNUM*CNUM];
__device__ float g_vec2[BNUM*2];
__device__ int   g_maxbuf[64];
__device__ __align__(16) float g_gate_raw[348160];
__device__ __align__(16) float g_gi[348160];

// ---------------- constants ----------------
__constant__ int   c_HW[4]      = {16384, 4096, 1024, 256};
__constant__ int   c_W[4]       = {128, 64, 32, 16};
__constant__ int   c_lw[4]      = {7, 6, 5, 4};
__constant__ int   c_pixBase[4] = {0, 262144, 327680, 344064};
__constant__ int   c_gateOut[4] = {89128960, 89391104, 89456640, 89473024};
__constant__ float c_step[4]    = {2.f/127.f, 2.f/63.f, 2.f/31.f, 2.f/15.f};

// ---------------- packed f32x2 helpers ----------------
__device__ __forceinline__ ull pk2(float lo, float hi) {
    ull r;
    asm("mov.b64 %0,{%1,%2};" : "=l"(r) : "f"(lo), "f"(hi));
    return r;
}
__device__ __forceinline__ void fma2(ull& d, ull a, ull b) {
    asm("fma.rn.f32x2 %0,%1,%2,%0;" : "+l"(d) : "l"(a), "l"(b));
}
__device__ __forceinline__ float2 unpk2(ull v) {
    float2 f;
    asm("mov.b64 {%0,%1},%2;" : "=f"(f.x), "=f"(f.y) : "l"(v));
    return f;
}

// ================= prep: blocks 0..79 = KV tiles (4 rows); 80..95 = mod MLPs =================
#define KV_ROWS 4
__global__ __launch_bounds__(256) void prep_kernel(
    const float* __restrict__ wt, const float* __restrict__ Wk, const float* __restrict__ Wv,
    const float* __restrict__ sent,
    const float* __restrict__ gw1, const float* __restrict__ gb1,
    const float* __restrict__ gw2, const float* __restrict__ gb2,
    const float* __restrict__ bw1, const float* __restrict__ bb1,
    const float* __restrict__ bw2, const float* __restrict__ bb2,
    const float* __restrict__ dw1, const float* __restrict__ db1,
    const float* __restrict__ dw2, const float* __restrict__ db2)
{
    __shared__ __align__(16) float swt[KV_ROWS*DT];
    __shared__ __align__(16) float ss[DT];
    __shared__ float sh[CNUM];
    int t = threadIdx.x;
    int bid = blockIdx.x;

    if (bid < 80) {
        if (bid == 0 && t < 64) g_maxbuf[t] = 0;
        int r0 = bid * KV_ROWS;
        for (int i = t; i < KV_ROWS*DT; i += 256) swt[i] = wt[(size_t)r0*DT + i];
        __syncthreads();
        float aK[KV_ROWS], aV[KV_ROWS];
#pragma unroll
        for (int r = 0; r < KV_ROWS; ++r) { aK[r] = 0.f; aV[r] = 0.f; }
        int c = t;
        for (int d = 0; d < DT; d += 4) {
            float k0 = Wk[(d+0)*CNUM + c], k1 = Wk[(d+1)*CNUM + c];
            float k2 = Wk[(d+2)*CNUM + c], k3 = Wk[(d+3)*CNUM + c];
            float v0 = Wv[(d+0)*CNUM + c], v1 = Wv[(d+1)*CNUM + c];
            float v2 = Wv[(d+2)*CNUM + c], v3 = Wv[(d+3)*CNUM + c];
#pragma unroll
            for (int r = 0; r < KV_ROWS; ++r) {
                float4 w = *reinterpret_cast<const float4*>(&swt[r*DT + d]);
                aK[r] = fmaf(w.x, k0, aK[r]); aK[r] = fmaf(w.y, k1, aK[r]);
                aK[r] = fmaf(w.z, k2, aK[r]); aK[r] = fmaf(w.w, k3, aK[r]);
                aV[r] = fmaf(w.x, v0, aV[r]); aV[r] = fmaf(w.y, v1, aV[r]);
                aV[r] = fmaf(w.z, v2, aV[r]); aV[r] = fmaf(w.w, v3, aV[r]);
            }
        }
#pragma unroll
        for (int r = 0; r < KV_ROWS; ++r) {
            g_K[(r0 + r)*CNUM + c] = aK[r];
            g_V[(r0 + r)*CNUM + c] = aV[r];
        }
    } else {
        int b = bid - 80;
        for (int i = t; i < DT; i += 256) ss[i] = sent[b*DT + i];
        __syncthreads();
        {
            float a0=0,a1=0,a2=0,a3=0;
            for (int d = 0; d < DT; d += 4) {
                float4 s = *reinterpret_cast<const float4*>(&ss[d]);
                a0 = fmaf(s.x, gw1[(d+0)*CNUM + t], a0);
                a1 = fmaf(s.y, gw1[(d+1)*CNUM + t], a1);
                a2 = fmaf(s.z, gw1[(d+2)*CNUM + t], a2);
                a3 = fmaf(s.w, gw1[(d+3)*CNUM + t], a3);
            }
            sh[t] = fmaxf((a0+a1)+(a2+a3) + gb1[t], 0.f);
        }
        __syncthreads();
        {
            float a0=0,a1=0,a2=0,a3=0;
            for (int j = 0; j < CNUM; j += 4) {
                float4 s = *reinterpret_cast<const float4*>(&sh[j]);
                a0 = fmaf(s.x, gw2[(j+0)*CNUM + t], a0);
                a1 = fmaf(s.y, gw2[(j+1)*CNUM + t], a1);
                a2 = fmaf(s.z, gw2[(j+2)*CNUM + t], a2);
                a3 = fmaf(s.w, gw2[(j+3)*CNUM + t], a3);
            }
            g_scale[b*CNUM + t] = 1.f + (a0+a1)+(a2+a3) + gb2[t];
        }
        __syncthreads();
        {
            float a0=0,a1=0,a2=0,a3=0;
            for (int d = 0; d < DT; d += 4) {
                float4 s = *reinterpret_cast<const float4*>(&ss[d]);
                a0 = fmaf(s.x, bw1[(d+0)*CNUM + t], a0);
                a1 = fmaf(s.y, bw1[(d+1)*CNUM + t], a1);
                a2 = fmaf(s.z, bw1[(d+2)*CNUM + t], a2);
                a3 = fmaf(s.w, bw1[(d+3)*CNUM + t], a3);
            }
            sh[t] = fmaxf((a0+a1)+(a2+a3) + bb1[t], 0.f);
        }
        __syncthreads();
        {
            float a0=0,a1=0,a2=0,a3=0;
            for (int j = 0; j < CNUM; j += 4) {
                float4 s = *reinterpret_cast<const float4*>(&sh[j]);
                a0 = fmaf(s.x, bw2[(j+0)*CNUM + t], a0);
                a1 = fmaf(s.y, bw2[(j+1)*CNUM + t], a1);
                a2 = fmaf(s.z, bw2[(j+2)*CNUM + t], a2);
                a3 = fmaf(s.w, bw2[(j+3)*CNUM + t], a3);
            }
            g_beta[b*CNUM + t] = (a0+a1)+(a2+a3) + bb2[t];
        }
        __syncthreads();
        if (t < 64) {
            float a0=0,a1=0,a2=0,a3=0;
            for (int d = 0; d < DT; d += 4) {
                float4 s = *reinterpret_cast<const float4*>(&ss[d]);
                a0 = fmaf(s.x, dw1[(d+0)*64 + t], a0);
                a1 = fmaf(s.y, dw1[(d+1)*64 + t], a1);
                a2 = fmaf(s.z, dw1[(d+2)*64 + t], a2);
                a3 = fmaf(s.w, dw1[(d+3)*64 + t], a3);
            }
            sh[t] = fmaxf((a0+a1)+(a2+a3) + db1[t], 0.f);
        }
        __syncthreads();
        if (t == 0) {
            float v0 = db2[0], v1 = db2[1];
            for (int j = 0; j < 64; ++j) {
                v0 = fmaf(sh[j], dw2[j*2 + 0], v0);
                v1 = fmaf(sh[j], dw2[j*2 + 1], v1);
            }
            float nrm = fmaxf(sqrtf(v0*v0 + v1*v1), 1e-12f);
            g_vec2[b*2 + 0] = v0 / nrm;
            g_vec2[b*2 + 1] = v1 / nrm;
        }
    }
}

// ================= blocks 0..79: M = (K@Wq)/16; 80..95: G = V@V^T =================
__global__ __launch_bounds__(256) void mv_kernel(const float* __restrict__ Wq) {
    __shared__ __align__(16) float sK[KV_ROWS*CNUM];
    __shared__ __align__(16) float sV[LNUM*CNUM];
    int t = threadIdx.x;
    int bid = blockIdx.x;
    if (bid < 80) {
        int r0 = bid * KV_ROWS;
        for (int i = t; i < KV_ROWS*CNUM; i += 256) sK[i] = g_K[r0*CNUM + i];
        __syncthreads();
        float acc[KV_ROWS];
#pragma unroll
        for (int r = 0; r < KV_ROWS; ++r) acc[r] = 0.f;
        int c = t;
        for (int o = 0; o < CNUM; o += 4) {
            float q0 = Wq[(o+0)*CNUM + c], q1 = Wq[(o+1)*CNUM + c];
            float q2 = Wq[(o+2)*CNUM + c], q3 = Wq[(o+3)*CNUM + c];
#pragma unroll
            for (int r = 0; r < KV_ROWS; ++r) {
                float4 k = *reinterpret_cast<const float4*>(&sK[r*CNUM + o]);
                acc[r] = fmaf(k.x, q0, acc[r]); acc[r] = fmaf(k.y, q1, acc[r]);
                acc[r] = fmaf(k.z, q2, acc[r]); acc[r] = fmaf(k.w, q3, acc[r]);
            }
        }
#pragma unroll
        for (int r = 0; r < KV_ROWS; ++r)
            g_M[(r0 + r)*CNUM + c] = acc[r] * 0.0625f;
    } else {
        int b = bid - 80;
        for (int i = t; i < LNUM*CNUM; i += 256) sV[i] = g_V[b*LNUM*CNUM + i];
        __syncthreads();
        for (int e = t; e < LNUM*LNUM; e += 256) {
            int l  = e / LNUM;
            int l2 = e % LNUM;
            float a0=0,a1=0,a2=0,a3=0;
            for (int c = 0; c < CNUM; c += 4) {
                float4 x = *reinterpret_cast<const float4*>(&sV[l*CNUM + c]);
                float4 y = *reinterpret_cast<const float4*>(&sV[l2*CNUM + c]);
                a0 = fmaf(x.x, y.x, a0); a1 = fmaf(x.y, y.y, a1);
                a2 = fmaf(x.z, y.z, a2); a3 = fmaf(x.w, y.w, a3);
            }
            g_G[b*LNUM*LNUM + e] = (a0+a1)+(a2+a3);
        }
    }
}

// ---------------- block decode: 688 blocks ----------------
__device__ __forceinline__ void decode_block(int bid, int& level, int& b, int& tile) {
    if (bid < 512)      { level = 0; b = bid >> 5; tile = bid & 31; }
    else if (bid < 640) { int r = bid - 512; level = 1; b = r >> 3; tile = r & 7; }
    else if (bid < 672) { int r = bid - 640; level = 2; b = r >> 1; tile = r & 1; }
    else                { level = 3; b = bid - 672; tile = 0; }
}

// ---------------- phaseA core ----------------
template<int HW>
__device__ __forceinline__ void phaseA_core(const float* __restrict__ F, int b, int n0,
                                            const ull* __restrict__ sM2,
                                            const ull* __restrict__ sG2,
                                            const int* __restrict__ smask,
                                            int pbase, int maxSlot) {
    const float* p = F + (size_t)b * CNUM * HW + n0;

    ull acc[LNUM];
#pragma unroll
    for (int l = 0; l < LNUM; ++l) acc[l] = 0ull;

    // logits: pixel-packed; streaming loads (F read once, no L2 reuse)
#pragma unroll 8
    for (int c = 0; c < CNUM; c += 2) {
        ull fa = __ldcs(reinterpret_cast<const ull*>(p));
        ull fb = __ldcs(reinterpret_cast<const ull*>(p + HW));
        p += 2 * HW;
#pragma unroll
        for (int l = 0; l < LNUM; ++l) {
            ulonglong2 m = *reinterpret_cast<const ulonglong2*>(&sM2[l*CNUM + c]);
            fma2(acc[l], fa, m.x);
            fma2(acc[l], fb, m.y);
        }
    }

    // lane-wise masked softmax (normalization folded into gate)
    float2 mx = make_float2(-1e30f, -1e30f);
#pragma unroll
    for (int l = 0; l < LNUM; ++l) {
        if (smask[l]) {
            float2 u = unpk2(acc[l]);
            mx.x = fmaxf(mx.x, u.x);
            mx.y = fmaxf(mx.y, u.y);
        }
    }
    float2 sm = make_float2(0.f, 0.f);
#pragma unroll
    for (int l = 0; l < LNUM; ++l) {
        int mk = smask[l];
        float2 u = unpk2(acc[l]);
        float e0 = mk ? __expf(u.x - mx.x) : 0.f;
        float e1 = mk ? __expf(u.y - mx.y) : 0.f;
        sm.x += e0; sm.y += e1;
        acc[l] = pk2(e0, e1);
    }

    // gate = sqrt(e^T G e) / sum(e)
    ull gs = 0ull;
#pragma unroll
    for (int l = 0; l < LNUM; ++l) {
        ull tt = 0ull;
#pragma unroll
        for (int l2 = 0; l2 < LNUM; l2 += 2) {
            ulonglong2 gg = *reinterpret_cast<const ulonglong2*>(&sG2[l*LNUM + l2]);
            fma2(tt, acc[l2],   gg.x);
            fma2(tt, acc[l2+1], gg.y);
        }
        fma2(gs, acc[l], tt);
    }
    float2 g0 = unpk2(gs);
    float2 gt;
    gt.x = sqrtf(fmaxf(g0.x, 0.f)) * __fdividef(1.f, sm.x);
    gt.y = sqrtf(fmaxf(g0.y, 0.f)) * __fdividef(1.f, sm.y);
    *reinterpret_cast<float2*>(&g_gate_raw[pbase + n0]) = gt;
    atomicMax(&g_maxbuf[maxSlot], __float_as_int(fmaxf(gt.x, gt.y)));
}

// ================= Phase A =================
__global__ __launch_bounds__(256, 3) void phaseA(const float* __restrict__ f0,
                                                 const float* __restrict__ f1,
                                                 const float* __restrict__ f2,
                                                 const float* __restrict__ f3,
                                                 const int* __restrict__ mask) {
    __shared__ __align__(16) ull sM2[LNUM*CNUM];   // (m,m) pairs, 40KB
    __shared__ __align__(16) ull sG2[LNUM*LNUM];   // (g,g) pairs
    __shared__ int smask[LNUM];

    int level, b, tile;
    decode_block(blockIdx.x, level, b, tile);
    int t = threadIdx.x;
    int bbase = b * LNUM * CNUM;
    for (int i = t; i < LNUM*CNUM; i += 256) { float m = g_M[bbase + i]; sM2[i] = pk2(m, m); }
    for (int i = t; i < LNUM*LNUM; i += 256) { float g = g_G[b*LNUM*LNUM + i]; sG2[i] = pk2(g, g); }
    if (t < LNUM) smask[t] = mask[b*LNUM + t];
    __syncthreads();

    int n0 = tile * 512 + 2 * t;
    if (level == 0)
        phaseA_core<16384>(f0, b, n0, sM2, sG2, smask, b*16384,          b);
    else if (level == 1)
        phaseA_core< 4096>(f1, b, n0, sM2, sG2, smask, 262144 + b*4096, 16 + b);
    else if (level == 2)
        phaseA_core< 1024>(f2, b, n0, sM2, sG2, smask, 327680 + b*1024, 32 + b);
    else if (t < 128)
        phaseA_core<  256>(f3, b, 2*t, sM2, sG2, smask, 344064 + b*256, 48 + b);
}

// ================= Phase A2 =================
__global__ __launch_bounds__(256) void phaseA2(float* __restrict__ out) {
    int level, b, tile;
    decode_block(blockIdx.x, level, b, tile);
    int t = threadIdx.x;
    const int HW = c_HW[level];
    const int W  = c_W[level];
    const int lw = c_lw[level];
    float step = c_step[level];
    float v0 = g_vec2[2*b], v1 = g_vec2[2*b + 1];
    float mxv = __int_as_float(g_maxbuf[level*16 + b]) + 1e-6f;
    int pbase = c_pixBase[level] + b*HW;
    int obase = c_gateOut[level] + b*HW;
#pragma unroll
    for (int p = 0; p < 2; ++p) {
        int n = tile * 512 + t + p * 256;
        if (n >= HW) break;
        int w = n & (W - 1);
        int h = n >> lw;
        float x = fmaf((float)w, step, -1.f);
        float y = fmaf((float)h, step, -1.f);
        float pr = v0 * x + v1 * y;
        float di = __fdividef(1.f, 1.f + __expf(-pr));
        float gi = __fdividef(g_gate_raw[pbase + n], mxv) * di;
        g_gi[pbase + n] = gi;
        out[obase + n] = gi;
    }
}

// ================= Phase B =================
template<int HW, int LG>
__device__ __forceinline__ void phaseB_core(const float* __restrict__ F,
                                            float* __restrict__ out,
                                            int g, int pixBase) {
    int n4   = g & (HW/4 - 1);
    int rest = g >> LG;
    int c = rest & 255;
    int b = rest >> 8;
    float sc = g_scale[b*CNUM + c];
    float be = g_beta[b*CNUM + c];
    const float4* fp = reinterpret_cast<const float4*>(F) + g;
    const float4* gp = reinterpret_cast<const float4*>(&g_gi[pixBase + b*HW]) + n4;
    float4*       op = reinterpret_cast<float4*>(out) + g;
#pragma unroll
    for (int j = 0; j < 4; ++j) {
        float4 f  = __ldcs(&fp[j]);
        float4 gi = gp[j];
        float4 o;
        o.x = fmaf(gi.x * f.x, sc, be);
        o.y = fmaf(gi.y * f.y, sc, be);
        o.z = fmaf(gi.z * f.z, sc, be);
        o.w = fmaf(gi.w * f.w, sc, be);
        __stcs(&op[j], o);
    }
}

__global__ __launch_bounds__(256) void phaseB(const float* __restrict__ f0,
                                              const float* __restrict__ f1,
                                              const float* __restrict__ f2,
                                              const float* __restrict__ f3,
                                              float* __restrict__ out) {
    int bid = blockIdx.x;
    int t = threadIdx.x;
    if (bid < 16384) {
        int g = bid * 1024 + t * 4;
        phaseB_core<16384, 12>(f0, out, g, 0);
    } else if (bid < 20480) {
        int g = (bid - 16384) * 1024 + t * 4;
        phaseB_core<4096, 10>(f1, out + 67108864, g, 262144);
    } else if (bid < 21504) {
        int g = (bid - 20480) * 1024 + t * 4;
        phaseB_core<1024, 8>(f2, out + 83886080, g, 327680);
    } else {
        int g = (bid - 21504) * 1024 + t * 4;
        phaseB_core<256, 6>(f3, out + 88080384, g, 344064);
    }
}

// ================= launch =================
extern "C" void kernel_launch(void* const* d_in, const int* in_sizes, int n_in,
                              void* d_out, int out_size) {
    const float* f0   = (const float*)d_in[0];
    const float* f1   = (const float*)d_in[1];
    const float* f2   = (const float*)d_in[2];
    const float* f3   = (const float*)d_in[3];
    const float* wt   = (const float*)d_in[4];
    const float* sent = (const float*)d_in[5];
    const int*   mask = (const int*)  d_in[6];
    const float* Wq   = (const float*)d_in[7];
    const float* Wk   = (const float*)d_in[8];
    const float* Wv   = (const float*)d_in[9];
    const float* gw1  = (const float*)d_in[10];
    const float* gb1  = (const float*)d_in[11];
    const float* gw2  = (const float*)d_in[12];
    const float* gb2  = (const float*)d_in[13];
    const float* bw1  = (const float*)d_in[14];
    const float* bb1  = (const float*)d_in[15];
    const float* bw2  = (const float*)d_in[16];
    const float* bb2  = (const float*)d_in[17];
    const float* dw1  = (const float*)d_in[18];
    const float* db1  = (const float*)d_in[19];
    const float* dw2  = (const float*)d_in[20];
    const float* db2  = (const float*)d_in[21];
    float* out = (float*)d_out;

    prep_kernel<<<96, 256>>>(wt, Wk, Wv, sent, gw1, gb1, gw2, gb2,
                             bw1, bb1, bw2, bb2, dw1, db1, dw2, db2);
    mv_kernel<<<96, 256>>>(Wq);
    phaseA<<<688, 256>>>(f0, f1, f2, f3, mask);
    phaseA2<<<688, 256>>>(out);
    phaseB<<<21760, 256>>>(f0, f1, f2, f3, out);
}